// round 11
// baseline (speedup 1.0000x reference)
#include <cuda_runtime.h>
#include <cuda_bf16.h>
#include <math.h>
#include <stdint.h>

// ---------------- problem constants ----------------
#define BB 64      // batch
#define SS 128     // seq len
#define LW 20      // chars per word
#define CE 30      // char emb
#define CC 30      // char conv channels
#define WE 300     // word emb
#define HH 256     // hidden
#define NCL 25     // num classes
#define FF 330     // feature = WE + CC
#define KPAD 384   // padded K for bf16 MMA (6 chunks of 64)
#define NROW 8192  // S*B token rows
#define N2 2048    // 2 dirs * 4H

// ---------------- packed f32x2 helpers ----------------
#define FMA2(d, a, b) asm("fma.rn.f32x2 %0, %1, %2, %0;" : "+l"(d) : "l"(a), "l"(b))

__device__ __forceinline__ float2 unpk(unsigned long long v) {
    float2 f;
    asm("mov.b64 {%0, %1}, %2;" : "=f"(f.x), "=f"(f.y) : "l"(v));
    return f;
}

// ---------------- mma.sync / async helpers (baseline PTX, sm_103-safe) ------
__device__ __forceinline__ uint32_t smem_u32(const void* p) {
    uint32_t a;
    asm("{ .reg .u64 t; cvta.to.shared.u64 t, %1; cvt.u32.u64 %0, t; }" : "=r"(a) : "l"(p));
    return a;
}
#define SWZ(o) ((o) ^ (((o) >> 3) & 0x70))

#define LDSM_X4(r0, r1, r2, r3, a) \
    asm volatile("ldmatrix.sync.aligned.m8n8.x4.shared.b16 {%0,%1,%2,%3}, [%4];" \
                 : "=r"(r0), "=r"(r1), "=r"(r2), "=r"(r3) : "r"(a))

#define MMA_BF16(c0, c1, c2, c3, a0, a1, a2, a3, b0, b1) \
    asm volatile("mma.sync.aligned.m16n8k16.row.col.f32.bf16.bf16.f32 " \
                 "{%0,%1,%2,%3}, {%4,%5,%6,%7}, {%8,%9}, {%0,%1,%2,%3};" \
                 : "+f"(c0), "+f"(c1), "+f"(c2), "+f"(c3) \
                 : "r"(a0), "r"(a1), "r"(a2), "r"(a3), "r"(b0), "r"(b1))

#define CP_ASYNC16(dst, src) \
    asm volatile("cp.async.cg.shared.global [%0], [%1], 16;" :: "r"(dst), "l"(src))
#define CP_COMMIT() asm volatile("cp.async.commit_group;")
#define CP_WAIT(n)  asm volatile("cp.async.wait_group %0;" :: "n"(n))

// ---------------- static device scratch ----------------
__device__ __align__(16) __nv_bfloat16 g_featH[(size_t)NROW * KPAD];  // hi
__device__ __align__(16) __nv_bfloat16 g_featL[(size_t)NROW * KPAD];  // lo residual
__device__ __align__(16) __nv_bfloat16 g_wH[(size_t)N2 * KPAD];       // hi
__device__ __align__(16) __nv_bfloat16 g_wL[(size_t)N2 * KPAD];       // lo residual
__device__ float g_gx[(size_t)NROW * N2];     // [(t*2048+col)*64 + b]
__device__ float g_hT[2 * 2 * BB * HH];       // [dir][parity][b][u]
__device__ float g_hseq[(size_t)NROW * 512];  // [(t*512+ug)*64 + b]
__device__ float g_em[(size_t)NROW * NCL];    // [(t*64+b)*25 + c]
__device__ int   g_mask[BB * SS];             // [b][t]
__device__ float g_nll[BB];
__device__ int   g_flag[2][SS][64];           // per-step, per-block arrival flags

__device__ __forceinline__ float sigf(float x) { return 1.0f / (1.0f + __expf(-x)); }

__device__ __forceinline__ void split_bf16(float v, __nv_bfloat16& hi, __nv_bfloat16& lo) {
    hi = __float2bfloat16_rn(v);
    lo = __float2bfloat16_rn(v - __bfloat162float(hi));
}

// ---------------- init ----------------
__global__ void init_kernel() {
    int tid = blockIdx.x * blockDim.x + threadIdx.x;
    int nt = blockDim.x * gridDim.x;
    for (int i = tid; i < 2 * SS * 64; i += nt) ((int*)g_flag)[i] = 0;
    for (int i = tid; i < 2 * 2 * BB * HH; i += nt) g_hT[i] = 0.0f;
    if (tid < BB) g_nll[tid] = 0.0f;
}

// ---------------- mask dtype detect + convert ----------------
__global__ void mask_convert_kernel(const unsigned* __restrict__ m) {
    unsigned v0 = m[0];
    int mode;  // 0 = int32, 1 = bytes, 2 = float32
    if (v0 == 0x01010101u) mode = 1;
    else if (v0 == 0x3F800000u) mode = 2;
    else mode = 0;
    int tid = blockIdx.x * blockDim.x + threadIdx.x;
    if (tid >= BB * SS) return;
    int v;
    if (mode == 1) {
        const unsigned char* mb = (const unsigned char*)m;
        v = (mb[tid] != 0) ? 1 : 0;
    } else if (mode == 2) {
        const float* mf = (const float*)m;
        v = (mf[tid] != 0.0f) ? 1 : 0;
    } else {
        v = (m[tid] != 0u) ? 1 : 0;
    }
    g_mask[tid] = v;
}

// ---------------- pad w_ih into bf16 hi/lo [2048][384] ----------------
__global__ void pad_w_kernel(const float* __restrict__ w_ih_f,
                             const float* __restrict__ w_ih_r) {
    int idx = blockIdx.x * blockDim.x + threadIdx.x;
    if (idx >= N2 * KPAD) return;
    int r = idx / KPAD, k = idx - r * KPAD;
    float v = 0.0f;
    if (k < FF) v = (r < 1024) ? w_ih_f[r * FF + k] : w_ih_r[(r - 1024) * FF + k];
    __nv_bfloat16 hi, lo;
    split_bf16(v, hi, lo);
    g_wH[idx] = hi;
    g_wL[idx] = lo;
}

// ---------------- char CNN + embedding concat -> featH/L (bf16) -------------
__global__ __launch_bounds__(128) void embed_conv_kernel(
    const float* __restrict__ word_table, const float* __restrict__ char_table,
    const float* __restrict__ conv_w, const float* __restrict__ conv_b,
    const int* __restrict__ sent, const int* __restrict__ word) {
    __shared__ float wsm[CC * CE * 3];   // 2700
    __shared__ float psm[4][22 * 32];    // per-warp padded char emb [pos][ic(32)]
    __shared__ int   cids[4][LW];

    int tid = threadIdx.x, w = tid >> 5, lane = tid & 31;
    int tok = blockIdx.x * 4 + w;        // tok = b*128 + s
    int b = tok >> 7, s = tok & 127;
    int row = s * BB + b;

    for (int i = tid; i < CC * CE * 3; i += 128) wsm[i] = conv_w[i];
    float* pw = psm[w];
    for (int i = lane; i < 22 * 32; i += 32) pw[i] = 0.0f;
    if (lane < LW) cids[w][lane] = word[tok * LW + lane];
    __syncthreads();

    for (int pos = 0; pos < LW; pos++) {
        if (lane < CE) {
            int c = cids[w][pos];
            pw[(pos + 1) * 32 + lane] = (c == 0) ? 0.0f : char_table[c * CE + lane];
        }
    }

    // word embedding copy (fp32 -> bf16 hi/lo)
    int widx = sent[tok];
    __nv_bfloat16* frowH = g_featH + (size_t)row * KPAD;
    __nv_bfloat16* frowL = g_featL + (size_t)row * KPAD;
    {
        const float4* wt = (const float4*)(word_table + (size_t)widx * WE);
        for (int j = lane; j < 75; j += 32) {
            float4 v = wt[j];
            __nv_bfloat16 h0, l0, h1, l1, h2, l2, h3, l3;
            split_bf16(v.x, h0, l0); split_bf16(v.y, h1, l1);
            split_bf16(v.z, h2, l2); split_bf16(v.w, h3, l3);
            __nv_bfloat162 ph0; ph0.x = h0; ph0.y = h1;
            __nv_bfloat162 ph1; ph1.x = h2; ph1.y = h3;
            __nv_bfloat162 pl0; pl0.x = l0; pl0.y = l1;
            __nv_bfloat162 pl1; pl1.x = l2; pl1.y = l3;
            *(__nv_bfloat162*)(frowH + j * 4) = ph0;
            *(__nv_bfloat162*)(frowH + j * 4 + 2) = ph1;
            *(__nv_bfloat162*)(frowL + j * 4) = pl0;
            *(__nv_bfloat162*)(frowL + j * 4 + 2) = pl1;
        }
    }
    __syncwarp();

    // conv: lane oc, weights in regs, x broadcast
    int oc = (lane < CC) ? lane : 0;
    float wreg[3][32];
#pragma unroll
    for (int k = 0; k < 3; k++)
#pragma unroll
        for (int ic = 0; ic < 32; ic++)
            wreg[k][ic] = (ic < CC) ? wsm[oc * 90 + ic * 3 + k] : 0.0f;

    float m = -1e30f;
    for (int t = 0; t < LW; t++) {
        float asum = 0.0f;
#pragma unroll
        for (int k = 0; k < 3; k++) {
            const float4* xr = (const float4*)(pw + (t + k) * 32);
            float acc = 0.0f;
#pragma unroll
            for (int j = 0; j < 8; j++) {
                float4 x = xr[j];
                acc += x.x * wreg[k][j * 4 + 0] + x.y * wreg[k][j * 4 + 1]
                     + x.z * wreg[k][j * 4 + 2] + x.w * wreg[k][j * 4 + 3];
            }
            asum += acc;
        }
        m = fmaxf(m, asum);
    }
    if (lane < CC) {
        __nv_bfloat16 hi, lo;
        split_bf16(m + conv_b[lane], hi, lo);
        frowH[WE + lane] = hi;
        frowL[WE + lane] = lo;
    }
    if (lane < 27) {
        __nv_bfloat162 z; z.x = __float2bfloat16_rn(0.0f); z.y = z.x;
        *(__nv_bfloat162*)(frowH + FF + 2 * lane) = z;
        *(__nv_bfloat162*)(frowL + FF + 2 * lane) = z;
    }
}

// ---------------- gx GEMM via mma.sync bf16, split hi/lo 3-pass -------------
#define GX_SMEM 69632
__global__ __launch_bounds__(256) void gemm_gx_mma_kernel(const float* __restrict__ bf,
                                                          const float* __restrict__ br) {
    extern __shared__ char smem[];
    uint32_t sbase = smem_u32(smem);
    int tid = threadIdx.x;
    int wid = tid >> 5, lane = tid & 31;
    int bn = blockIdx.x * 128;
    int bm = blockIdx.y * 128;

    int warp_m = wid & 1, warp_n = wid >> 1;
    int m0w = warp_m * 64, n0w = warp_n * 32;
    int g = lane >> 3;
    int rowA_off = (lane & 7) + (g & 1) * 8;
    int kA_off = (g >> 1) * 8;
    int rowB_off = (lane & 7) + (g >> 1) * 8;
    int kB_off = (g & 1) * 8;

    float acc[4][4][4];
#pragma unroll
    for (int i = 0; i < 4; i++)
#pragma unroll
        for (int j = 0; j < 4; j++)
#pragma unroll
            for (int q = 0; q < 4; q++) acc[i][j][q] = 0.0f;

    int srow = tid >> 3, su = tid & 7;
    const uint4* Agh = (const uint4*)(g_featH + (size_t)(bm + srow) * KPAD) + su;
    const uint4* Agl = (const uint4*)(g_featL + (size_t)(bm + srow) * KPAD) + su;
    const uint4* Bgh = (const uint4*)(g_wH + (size_t)(bn + srow) * KPAD) + su;
    const uint4* Bgl = (const uint4*)(g_wL + (size_t)(bn + srow) * KPAD) + su;

#pragma unroll 1
    for (int kc = 0; kc < 6; kc++) {
        if (kc > 0) __syncthreads();
#pragma unroll
        for (int j = 0; j < 4; j++) {
            size_t goff = (size_t)kc * 8 + (size_t)j * 32 * 48;
            uint32_t so = SWZ((srow + j * 32) * 128 + su * 16);
            *(uint4*)(smem + 0 + so)     = Agh[goff];
            *(uint4*)(smem + 16384 + so) = Bgh[goff];
            *(uint4*)(smem + 32768 + so) = Agl[goff];
            *(uint4*)(smem + 49152 + so) = Bgl[goff];
        }
        __syncthreads();

        uint32_t sAh = sbase, sBh = sbase + 16384, sAl = sbase + 32768, sBl = sbase + 49152;
#pragma unroll
        for (int ks = 0; ks < 4; ks++) {
            int k0 = ks * 16;
            uint32_t ah[4][4], al[4][4];
#pragma unroll
            for (int mt = 0; mt < 4; mt++) {
                int rowA = m0w + mt * 16 + rowA_off;
                uint32_t off = SWZ(rowA * 128 + (k0 + kA_off) * 2);
                LDSM_X4(ah[mt][0], ah[mt][1], ah[mt][2], ah[mt][3], sAh + off);
                LDSM_X4(al[mt][0], al[mt][1], al[mt][2], al[mt][3], sAl + off);
            }
            uint32_t bh[2][4], bl[2][4];
#pragma unroll
            for (int nt2 = 0; nt2 < 2; nt2++) {
                int rowB = n0w + nt2 * 16 + rowB_off;
                uint32_t off = SWZ(rowB * 128 + (k0 + kB_off) * 2);
                LDSM_X4(bh[nt2][0], bh[nt2][1], bh[nt2][2], bh[nt2][3], sBh + off);
                LDSM_X4(bl[nt2][0], bl[nt2][1], bl[nt2][2], bl[nt2][3], sBl + off);
            }
#pragma unroll
            for (int mt = 0; mt < 4; mt++) {
#pragma unroll
                for (int nt = 0; nt < 4; nt++) {
                    uint32_t bh0 = bh[nt >> 1][(nt & 1) * 2 + 0];
                    uint32_t bh1 = bh[nt >> 1][(nt & 1) * 2 + 1];
                    uint32_t bl0 = bl[nt >> 1][(nt & 1) * 2 + 0];
                    uint32_t bl1 = bl[nt >> 1][(nt & 1) * 2 + 1];
                    float* c = acc[mt][nt];
                    MMA_BF16(c[0], c[1], c[2], c[3],
                             ah[mt][0], ah[mt][1], ah[mt][2], ah[mt][3], bh0, bh1);
                    MMA_BF16(c[0], c[1], c[2], c[3],
                             ah[mt][0], ah[mt][1], ah[mt][2], ah[mt][3], bl0, bl1);
                    MMA_BF16(c[0], c[1], c[2], c[3],
                             al[mt][0], al[mt][1], al[mt][2], al[mt][3], bh0, bh1);
                }
            }
        }
    }
    __syncthreads();

    float* Ep = (float*)smem + wid * (64 * 34);
    int lr = lane >> 2, lc2 = (lane & 3) * 2;
#pragma unroll
    for (int mt = 0; mt < 4; mt++) {
#pragma unroll
        for (int nt = 0; nt < 4; nt++) {
            int r0 = mt * 16 + lr;
            int col = nt * 8 + lc2;
            *(float2*)&Ep[r0 * 34 + col] = make_float2(acc[mt][nt][0], acc[mt][nt][1]);
            *(float2*)&Ep[(r0 + 8) * 34 + col] = make_float2(acc[mt][nt][2], acc[mt][nt][3]);
        }
    }
    __syncwarp();

    int t = blockIdx.y * 2 + warp_m;
    int halfl = lane >> 4, b4 = lane & 15;
#pragma unroll
    for (int c = 0; c < 16; c++) {
        int n_local = c * 2 + halfl;
        int n = bn + n0w + n_local;
        float bias = (n < 1024) ? __ldg(&bf[n]) : __ldg(&br[n - 1024]);
        float4 v;
        v.x = Ep[(b4 * 4 + 0) * 34 + n_local] + bias;
        v.y = Ep[(b4 * 4 + 1) * 34 + n_local] + bias;
        v.z = Ep[(b4 * 4 + 2) * 34 + n_local] + bias;
        v.w = Ep[(b4 * 4 + 3) * 34 + n_local] + bias;
        *(float4*)&g_gx[((size_t)t * N2 + n) * 64 + b4 * 4] = v;
    }
}

// ---------------- persistent bidirectional LSTM ----------------
// Flag-array barrier (no atomic contention) + cp.async split-stage with
// k-split GEMV overlap.
#define LSTM_SMEM ((16 * 260 + 64 * 260 + 16 * 68) * 4)
__global__ __launch_bounds__(256, 1) void lstm_kernel(const float* __restrict__ whh_f,
                                                      const float* __restrict__ whh_r) {
    extern __shared__ float sm[];
    float* Ws = sm;                          // [16][260]
    float* Hs = sm + 16 * 260;               // [64][260]
    float* Pre = sm + 16 * 260 + 64 * 260;   // [16][68]

    int dir = blockIdx.x >> 6;
    int bslot = blockIdx.x & 63;
    int u0 = bslot * 4;
    const float* whh = dir ? whh_r : whh_f;
    int tid = threadIdx.x;
    uint32_t hs_u32 = smem_u32(Hs);

    int lane = tid & 31, w = tid >> 5;
    int r = lane & 15;
    int bh = lane >> 4;
    int bbase = w * 8 + bh * 4;
    int ab = tid & 63, au = tid >> 6;

    for (int i = tid; i < 16 * 256; i += 256) {
        int rr = i >> 8, k = i & 255;
        int g = rr >> 2, jj = rr & 3;
        Ws[rr * 260 + k] = whh[(size_t)(g * 256 + u0 + jj) * 256 + k];
    }

    float c = 0.0f;
    int p = 0;

    for (int step = 0; step < 128; step++) {
        int t = dir ? (127 - step) : step;

        // prefetch gx for this step (latency hides under barrier wait)
        size_t gxb = ((size_t)t * N2 + dir * 1024 + u0 + au) * 64 + ab;
        float ga0 = g_gx[gxb + 0 * 256 * 64];
        float ga1 = g_gx[gxb + 1 * 256 * 64];
        float ga2 = g_gx[gxb + 2 * 256 * 64];
        float ga3 = g_gx[gxb + 3 * 256 * 64];

        // barrier: wait for all 64 blocks of this direction to finish step-1
        if (step) {
            if (tid < 64) {
                volatile int* f = &g_flag[dir][step][tid];
                while (*f == 0) {}
            }
        }
        __syncthreads();

        // stage prev h in two k-halves via cp.async (L2 path)
        const float* hbase = g_hT + (size_t)(dir * 2 + p) * (BB * HH);
#pragma unroll
        for (int half = 0; half < 2; half++) {
#pragma unroll
            for (int jj = 0; jj < 8; jj++) {
                int c2 = jj * 256 + tid;       // 0..2047
                int b = c2 >> 5, kc = c2 & 31;
                int col = half * 128 + kc * 4;
                CP_ASYNC16(hs_u32 + (b * 260 + col) * 4, hbase + b * 256 + col);
            }
            CP_COMMIT();
        }

        unsigned long long A0 = 0ull, A1 = 0ull, A2 = 0ull, A3 = 0ull;
        const float* wrow = Ws + r * 260;
        const float* h0 = Hs + (bbase + 0) * 260;
        const float* h1 = Hs + (bbase + 1) * 260;
        const float* h2 = Hs + (bbase + 2) * 260;
        const float* h3 = Hs + (bbase + 3) * 260;

        CP_WAIT(1);
        __syncthreads();
        // GEMV k 0..127 (half 1 still in flight)
#pragma unroll 8
        for (int k = 0; k < 128; k += 4) {
            ulonglong2 wv = *(const ulonglong2*)(wrow + k);
            ulonglong2 x0 = *(const ulonglong2*)(h0 + k);
            ulonglong2 x1 = *(const ulonglong2*)(h1 + k);
            ulonglong2 x2 = *(const ulonglong2*)(h2 + k);
            ulonglong2 x3 = *(const ulonglong2*)(h3 + k);
            FMA2(A0, wv.x, x0.x); FMA2(A0, wv.y, x0.y);
            FMA2(A1, wv.x, x1.x); FMA2(A1, wv.y, x1.y);
            FMA2(A2, wv.x, x2.x); FMA2(A2, wv.y, x2.y);
            FMA2(A3, wv.x, x3.x); FMA2(A3, wv.y, x3.y);
        }
        CP_WAIT(0);
        __syncthreads();
        // GEMV k 128..255
#pragma unroll 8
        for (int k = 128; k < 256; k += 4) {
            ulonglong2 wv = *(const ulonglong2*)(wrow + k);
            ulonglong2 x0 = *(const ulonglong2*)(h0 + k);
            ulonglong2 x1 = *(const ulonglong2*)(h1 + k);
            ulonglong2 x2 = *(const ulonglong2*)(h2 + k);
            ulonglong2 x3 = *(const ulonglong2*)(h3 + k);
            FMA2(A0, wv.x, x0.x); FMA2(A0, wv.y, x0.y);
            FMA2(A1, wv.x, x1.x); FMA2(A1, wv.y, x1.y);
            FMA2(A2, wv.x, x2.x); FMA2(A2, wv.y, x2.y);
            FMA2(A3, wv.x, x3.x); FMA2(A3, wv.y, x3.y);
        }
        {
            float2 f0 = unpk(A0), f1 = unpk(A1), f2 = unpk(A2), f3 = unpk(A3);
            Pre[r * 68 + bbase + 0] = f0.x + f0.y;
            Pre[r * 68 + bbase + 1] = f1.x + f1.y;
            Pre[r * 68 + bbase + 2] = f2.x + f2.y;
            Pre[r * 68 + bbase + 3] = f3.x + f3.y;
        }
        __syncthreads();

        float a0 = ga0 + Pre[(0 * 4 + au) * 68 + ab];
        float a1 = ga1 + Pre[(1 * 4 + au) * 68 + ab];
        float a2 = ga2 + Pre[(2 * 4 + au) * 68 + ab];
        float a3 = ga3 + Pre[(3 * 4 + au) * 68 + ab];

        float ig = sigf(a0), fg = sigf(a1), gg = tanhf(a2), og = sigf(a3);
        c = fg * c + ig * gg;
        float h = og * tanhf(c);

        int pn = p ^ 1;
        g_hT[(size_t)(dir * 2 + pn) * (BB * HH) + ab * 256 + (u0 + au)] = h;
        g_hseq[((size_t)t * 512 + dir * 256 + u0 + au) * 64 + ab] = h;
        p = pn;

        // signal arrival for next step: all h stores done -> fence -> flag
        __syncthreads();
        if (step < 127 && tid == 0) {
            __threadfence();
            *(volatile int*)&g_flag[dir][step + 1][bslot] = 1;
        }
    }
}

// ---------------- emission: em = h @ lin_w^T + lin_b ----------------
#define EM_SMEM (NCL * 512 * 4)
__global__ __launch_bounds__(256) void emission_kernel(const float* __restrict__ lin_w,
                                                       const float* __restrict__ lin_b) {
    extern __shared__ float EWs[];
    int t = blockIdx.x;
    int tid = threadIdx.x;
    for (int i = tid; i < NCL * 512; i += 256) EWs[i] = lin_w[i];
    __syncthreads();

    int b = tid & 63, cg = tid >> 6;
    float acc[7];
#pragma unroll
    for (int ci = 0; ci < 7; ci++) {
        int c0 = cg * 7 + ci;
        acc[ci] = (c0 < NCL) ? lin_b[c0] : 0.0f;
    }
    const float* hp = g_hseq + (size_t)t * 512 * 64 + b;
#pragma unroll 4
    for (int u = 0; u < 512; u++) {
        float hv = hp[(size_t)u * 64];
#pragma unroll
        for (int ci = 0; ci < 7; ci++) {
            int c0 = cg * 7 + ci;
            if (c0 < NCL) acc[ci] += hv * EWs[c0 * 512 + u];
        }
    }
#pragma unroll
    for (int ci = 0; ci < 7; ci++) {
        int c0 = cg * 7 + ci;
        if (c0 < NCL) g_em[((size_t)t * 64 + b) * NCL + c0] = acc[ci];
    }
}

// ---------------- CRF NLL (one block per batch, 1 warp) ----------------
__global__ __launch_bounds__(32) void crf_kernel(const int* __restrict__ tag,
                                                 const float* __restrict__ start_t,
                                                 const float* __restrict__ end_t,
                                                 const float* __restrict__ trans) {
    int b = blockIdx.x;
    int lane = threadIdx.x;

    __shared__ float tr[NCL * NCL];
    __shared__ float alphas[32];

    for (int i = lane; i < NCL * NCL; i += 32) tr[i] = trans[i];
    __syncwarp();

    float myscore = 0.0f;
    int mylen = 0;
    for (int t = lane; t < SS; t += 32) {
        int mk = g_mask[b * SS + t];
        mylen += mk;
        int tgt = tag[b * SS + t];
        if (t == 0) {
            myscore += start_t[tgt] + g_em[(size_t)b * NCL + tgt];
        } else if (mk) {
            int tgp = tag[b * SS + t - 1];
            myscore += tr[tgp * NCL + tgt] + g_em[((size_t)t * 64 + b) * NCL + tgt];
        }
    }
#pragma unroll
    for (int off = 16; off > 0; off >>= 1) {
        myscore += __shfl_xor_sync(0xFFFFFFFFu, myscore, off);
        mylen += __shfl_xor_sync(0xFFFFFFFFu, mylen, off);
    }
    float score = 0.0f;
    if (lane == 0) {
        int last = mylen - 1;
        score = myscore + end_t[tag[b * SS + last]];
    }

    if (lane < NCL) alphas[lane] = start_t[lane] + g_em[(size_t)b * NCL + lane];
    __syncwarp();

    for (int t = 1; t < SS; t++) {
        int mk = g_mask[b * SS + t];
        float nxt = 0.0f;
        if (lane < NCL) {
            float emv = g_em[((size_t)t * 64 + b) * NCL + lane];
            float m = -1e30f;
#pragma unroll
            for (int i = 0; i < NCL; i++) m = fmaxf(m, alphas[i] + tr[i * NCL + lane]);
            float s = 0.0f;
#pragma unroll
            for (int i = 0; i < NCL; i++) s += __expf(alphas[i] + tr[i * NCL + lane] - m);
            nxt = m + __logf(s) + emv;
        }
        __syncwarp();
        if (lane < NCL && mk) alphas[lane] = nxt;
        __syncwarp();
    }

    float v = (lane < NCL) ? alphas[lane] + end_t[lane] : -1e30f;
    float m = v;
#pragma unroll
    for (int off = 16; off > 0; off >>= 1) m = fmaxf(m, __shfl_xor_sync(0xFFFFFFFFu, m, off));
    float s = __expf(v - m);
#pragma unroll
    for (int off = 16; off > 0; off >>= 1) s += __shfl_xor_sync(0xFFFFFFFFu, s, off);
    if (lane == 0) {
        float logZ = m + __logf(s);
        g_nll[b] = -(score - logZ);
    }
}

// ---------------- deterministic final sum ----------------
__global__ void sum_kernel(float* out) {
    int lane = threadIdx.x;
    float s = g_nll[lane] + g_nll[lane + 32];
#pragma unroll
    for (int off = 16; off > 0; off >>= 1) s += __shfl_xor_sync(0xFFFFFFFFu, s, off);
    if (lane == 0) out[0] = s;
}

// ---------------- launch ----------------
extern "C" void kernel_launch(void* const* d_in, const int* in_sizes, int n_in,
                              void* d_out, int out_size) {
    const float* word_table = (const float*)d_in[0];
    const float* char_table = (const float*)d_in[1];
    const float* conv_w     = (const float*)d_in[2];
    const float* conv_b     = (const float*)d_in[3];
    const float* w_ih_f     = (const float*)d_in[4];
    const float* w_hh_f     = (const float*)d_in[5];
    const float* b_f        = (const float*)d_in[6];
    const float* w_ih_r     = (const float*)d_in[7];
    const float* w_hh_r     = (const float*)d_in[8];
    const float* b_r        = (const float*)d_in[9];
    const float* lin_w      = (const float*)d_in[10];
    const float* lin_b      = (const float*)d_in[11];
    const float* start_t    = (const float*)d_in[12];
    const float* end_t      = (const float*)d_in[13];
    const float* trans      = (const float*)d_in[14];
    const int*   sent       = (const int*)d_in[15];
    const int*   word       = (const int*)d_in[16];
    const int*   tag        = (const int*)d_in[17];
    const unsigned* mask    = (const unsigned*)d_in[18];
    float* out = (float*)d_out;

    static int smem_set = 0;
    if (!smem_set) {
        cudaFuncSetAttribute(lstm_kernel, cudaFuncAttributeMaxDynamicSharedMemorySize, LSTM_SMEM);
        cudaFuncSetAttribute(emission_kernel, cudaFuncAttributeMaxDynamicSharedMemorySize, EM_SMEM);
        cudaFuncSetAttribute(gemm_gx_mma_kernel, cudaFuncAttributeMaxDynamicSharedMemorySize, GX_SMEM);
        smem_set = 1;
    }

    init_kernel<<<8, 256>>>();
    mask_convert_kernel<<<32, 256>>>(mask);
    pad_w_kernel<<<(N2 * KPAD + 255) / 256, 256>>>(w_ih_f, w_ih_r);
    embed_conv_kernel<<<2048, 128>>>(word_table, char_table, conv_w, conv_b, sent, word);
    gemm_gx_mma_kernel<<<dim3(16, 64), 256, GX_SMEM>>>(b_f, b_r);
    lstm_kernel<<<128, 256, LSTM_SMEM>>>(w_hh_f, w_hh_r);
    emission_kernel<<<128, 256, EM_SMEM>>>(lin_w, lin_b);
    crf_kernel<<<64, 32>>>(tag, start_t, end_t, trans);
    sum_kernel<<<1, 32>>>(out);
}

// round 12
// speedup vs baseline: 1.2302x; 1.2302x over previous
#include <cuda_runtime.h>
#include <cuda_bf16.h>
#include <math.h>
#include <stdint.h>

// ---------------- problem constants ----------------
#define BB 64      // batch
#define SS 128     // seq len
#define LW 20      // chars per word
#define CE 30      // char emb
#define CC 30      // char conv channels
#define WE 300     // word emb
#define HH 256     // hidden
#define NCL 25     // num classes
#define FF 330     // feature = WE + CC
#define KPAD 384   // padded K for bf16 MMA (6 chunks of 64)
#define NROW 8192  // S*B token rows
#define N2 2048    // 2 dirs * 4H

// ---------------- packed f32x2 helpers ----------------
#define FMA2(d, a, b) asm("fma.rn.f32x2 %0, %1, %2, %0;" : "+l"(d) : "l"(a), "l"(b))

__device__ __forceinline__ float2 unpk(unsigned long long v) {
    float2 f;
    asm("mov.b64 {%0, %1}, %2;" : "=f"(f.x), "=f"(f.y) : "l"(v));
    return f;
}

// ---------------- mma.sync / async helpers (baseline PTX, sm_103-safe) ------
__device__ __forceinline__ uint32_t smem_u32(const void* p) {
    uint32_t a;
    asm("{ .reg .u64 t; cvta.to.shared.u64 t, %1; cvt.u32.u64 %0, t; }" : "=r"(a) : "l"(p));
    return a;
}
#define SWZ(o) ((o) ^ (((o) >> 3) & 0x70))

#define LDSM_X4(r0, r1, r2, r3, a) \
    asm volatile("ldmatrix.sync.aligned.m8n8.x4.shared.b16 {%0,%1,%2,%3}, [%4];" \
                 : "=r"(r0), "=r"(r1), "=r"(r2), "=r"(r3) : "r"(a))

#define MMA_BF16(c0, c1, c2, c3, a0, a1, a2, a3, b0, b1) \
    asm volatile("mma.sync.aligned.m16n8k16.row.col.f32.bf16.bf16.f32 " \
                 "{%0,%1,%2,%3}, {%4,%5,%6,%7}, {%8,%9}, {%0,%1,%2,%3};" \
                 : "+f"(c0), "+f"(c1), "+f"(c2), "+f"(c3) \
                 : "r"(a0), "r"(a1), "r"(a2), "r"(a3), "r"(b0), "r"(b1))

#define CP_ASYNC16(dst, src) \
    asm volatile("cp.async.cg.shared.global [%0], [%1], 16;" :: "r"(dst), "l"(src))
#define CP_COMMIT() asm volatile("cp.async.commit_group;")
#define CP_WAIT(n)  asm volatile("cp.async.wait_group %0;" :: "n"(n))

// ---------------- static device scratch ----------------
__device__ __align__(16) __nv_bfloat16 g_featH[(size_t)NROW * KPAD];  // hi
__device__ __align__(16) __nv_bfloat16 g_featL[(size_t)NROW * KPAD];  // lo residual
__device__ __align__(16) __nv_bfloat16 g_wH[(size_t)N2 * KPAD];       // hi
__device__ __align__(16) __nv_bfloat16 g_wL[(size_t)N2 * KPAD];       // lo residual
__device__ float g_gx[(size_t)NROW * N2];     // [(t*2048+col)*64 + b]
__device__ float g_hT[2 * 2 * BB * HH];       // [dir][parity][b][u]
__device__ float g_hseq[(size_t)NROW * 512];  // [(t*512+ug)*64 + b]
__device__ float g_em[(size_t)NROW * NCL];    // [(t*64+b)*25 + c]
__device__ int   g_mask[BB * SS];             // [b][t]
__device__ float g_nll[BB];
__device__ unsigned g_cnt[2][SS];             // per-step arrival counters (single line poll)

__device__ __forceinline__ float sigf(float x) { return 1.0f / (1.0f + __expf(-x)); }

__device__ __forceinline__ void split_bf16(float v, __nv_bfloat16& hi, __nv_bfloat16& lo) {
    hi = __float2bfloat16_rn(v);
    lo = __float2bfloat16_rn(v - __bfloat162float(hi));
}

// ---------------- init ----------------
__global__ void init_kernel() {
    int tid = blockIdx.x * blockDim.x + threadIdx.x;
    int nt = blockDim.x * gridDim.x;
    for (int i = tid; i < 2 * SS; i += nt) ((unsigned*)g_cnt)[i] = 0u;
    for (int i = tid; i < 2 * 2 * BB * HH; i += nt) g_hT[i] = 0.0f;
    if (tid < BB) g_nll[tid] = 0.0f;
}

// ---------------- mask dtype detect + convert ----------------
__global__ void mask_convert_kernel(const unsigned* __restrict__ m) {
    unsigned v0 = m[0];
    int mode;  // 0 = int32, 1 = bytes, 2 = float32
    if (v0 == 0x01010101u) mode = 1;
    else if (v0 == 0x3F800000u) mode = 2;
    else mode = 0;
    int tid = blockIdx.x * blockDim.x + threadIdx.x;
    if (tid >= BB * SS) return;
    int v;
    if (mode == 1) {
        const unsigned char* mb = (const unsigned char*)m;
        v = (mb[tid] != 0) ? 1 : 0;
    } else if (mode == 2) {
        const float* mf = (const float*)m;
        v = (mf[tid] != 0.0f) ? 1 : 0;
    } else {
        v = (m[tid] != 0u) ? 1 : 0;
    }
    g_mask[tid] = v;
}

// ---------------- pad w_ih into bf16 hi/lo [2048][384] ----------------
__global__ void pad_w_kernel(const float* __restrict__ w_ih_f,
                             const float* __restrict__ w_ih_r) {
    int idx = blockIdx.x * blockDim.x + threadIdx.x;
    if (idx >= N2 * KPAD) return;
    int r = idx / KPAD, k = idx - r * KPAD;
    float v = 0.0f;
    if (k < FF) v = (r < 1024) ? w_ih_f[r * FF + k] : w_ih_r[(r - 1024) * FF + k];
    __nv_bfloat16 hi, lo;
    split_bf16(v, hi, lo);
    g_wH[idx] = hi;
    g_wL[idx] = lo;
}

// ---------------- char CNN + embedding concat -> featH/L (bf16) -------------
__global__ __launch_bounds__(128) void embed_conv_kernel(
    const float* __restrict__ word_table, const float* __restrict__ char_table,
    const float* __restrict__ conv_w, const float* __restrict__ conv_b,
    const int* __restrict__ sent, const int* __restrict__ word) {
    __shared__ float wsm[CC * CE * 3];   // 2700
    __shared__ float psm[4][22 * 32];    // per-warp padded char emb [pos][ic(32)]
    __shared__ int   cids[4][LW];

    int tid = threadIdx.x, w = tid >> 5, lane = tid & 31;
    int tok = blockIdx.x * 4 + w;        // tok = b*128 + s
    int b = tok >> 7, s = tok & 127;
    int row = s * BB + b;

    for (int i = tid; i < CC * CE * 3; i += 128) wsm[i] = conv_w[i];
    float* pw = psm[w];
    for (int i = lane; i < 22 * 32; i += 32) pw[i] = 0.0f;
    if (lane < LW) cids[w][lane] = word[tok * LW + lane];
    __syncthreads();

    for (int pos = 0; pos < LW; pos++) {
        if (lane < CE) {
            int c = cids[w][pos];
            pw[(pos + 1) * 32 + lane] = (c == 0) ? 0.0f : char_table[c * CE + lane];
        }
    }

    // word embedding copy (fp32 -> bf16 hi/lo)
    int widx = sent[tok];
    __nv_bfloat16* frowH = g_featH + (size_t)row * KPAD;
    __nv_bfloat16* frowL = g_featL + (size_t)row * KPAD;
    {
        const float4* wt = (const float4*)(word_table + (size_t)widx * WE);
        for (int j = lane; j < 75; j += 32) {
            float4 v = wt[j];
            __nv_bfloat16 h0, l0, h1, l1, h2, l2, h3, l3;
            split_bf16(v.x, h0, l0); split_bf16(v.y, h1, l1);
            split_bf16(v.z, h2, l2); split_bf16(v.w, h3, l3);
            __nv_bfloat162 ph0; ph0.x = h0; ph0.y = h1;
            __nv_bfloat162 ph1; ph1.x = h2; ph1.y = h3;
            __nv_bfloat162 pl0; pl0.x = l0; pl0.y = l1;
            __nv_bfloat162 pl1; pl1.x = l2; pl1.y = l3;
            *(__nv_bfloat162*)(frowH + j * 4) = ph0;
            *(__nv_bfloat162*)(frowH + j * 4 + 2) = ph1;
            *(__nv_bfloat162*)(frowL + j * 4) = pl0;
            *(__nv_bfloat162*)(frowL + j * 4 + 2) = pl1;
        }
    }
    __syncwarp();

    // conv: lane oc, weights in regs, x broadcast
    int oc = (lane < CC) ? lane : 0;
    float wreg[3][32];
#pragma unroll
    for (int k = 0; k < 3; k++)
#pragma unroll
        for (int ic = 0; ic < 32; ic++)
            wreg[k][ic] = (ic < CC) ? wsm[oc * 90 + ic * 3 + k] : 0.0f;

    float m = -1e30f;
    for (int t = 0; t < LW; t++) {
        float asum = 0.0f;
#pragma unroll
        for (int k = 0; k < 3; k++) {
            const float4* xr = (const float4*)(pw + (t + k) * 32);
            float acc = 0.0f;
#pragma unroll
            for (int j = 0; j < 8; j++) {
                float4 x = xr[j];
                acc += x.x * wreg[k][j * 4 + 0] + x.y * wreg[k][j * 4 + 1]
                     + x.z * wreg[k][j * 4 + 2] + x.w * wreg[k][j * 4 + 3];
            }
            asum += acc;
        }
        m = fmaxf(m, asum);
    }
    if (lane < CC) {
        __nv_bfloat16 hi, lo;
        split_bf16(m + conv_b[lane], hi, lo);
        frowH[WE + lane] = hi;
        frowL[WE + lane] = lo;
    }
    if (lane < 27) {
        __nv_bfloat162 z; z.x = __float2bfloat16_rn(0.0f); z.y = z.x;
        *(__nv_bfloat162*)(frowH + FF + 2 * lane) = z;
        *(__nv_bfloat162*)(frowL + FF + 2 * lane) = z;
    }
}

// ---------------- gx GEMM via mma.sync bf16, split hi/lo 3-pass -------------
#define GX_SMEM 69632
__global__ __launch_bounds__(256) void gemm_gx_mma_kernel(const float* __restrict__ bf,
                                                          const float* __restrict__ br) {
    extern __shared__ char smem[];
    uint32_t sbase = smem_u32(smem);
    int tid = threadIdx.x;
    int wid = tid >> 5, lane = tid & 31;
    int bn = blockIdx.x * 128;
    int bm = blockIdx.y * 128;

    int warp_m = wid & 1, warp_n = wid >> 1;
    int m0w = warp_m * 64, n0w = warp_n * 32;
    int g = lane >> 3;
    int rowA_off = (lane & 7) + (g & 1) * 8;
    int kA_off = (g >> 1) * 8;
    int rowB_off = (lane & 7) + (g >> 1) * 8;
    int kB_off = (g & 1) * 8;

    float acc[4][4][4];
#pragma unroll
    for (int i = 0; i < 4; i++)
#pragma unroll
        for (int j = 0; j < 4; j++)
#pragma unroll
            for (int q = 0; q < 4; q++) acc[i][j][q] = 0.0f;

    int srow = tid >> 3, su = tid & 7;
    const uint4* Agh = (const uint4*)(g_featH + (size_t)(bm + srow) * KPAD) + su;
    const uint4* Agl = (const uint4*)(g_featL + (size_t)(bm + srow) * KPAD) + su;
    const uint4* Bgh = (const uint4*)(g_wH + (size_t)(bn + srow) * KPAD) + su;
    const uint4* Bgl = (const uint4*)(g_wL + (size_t)(bn + srow) * KPAD) + su;

#pragma unroll 1
    for (int kc = 0; kc < 6; kc++) {
        if (kc > 0) __syncthreads();
#pragma unroll
        for (int j = 0; j < 4; j++) {
            size_t goff = (size_t)kc * 8 + (size_t)j * 32 * 48;
            uint32_t so = SWZ((srow + j * 32) * 128 + su * 16);
            *(uint4*)(smem + 0 + so)     = Agh[goff];
            *(uint4*)(smem + 16384 + so) = Bgh[goff];
            *(uint4*)(smem + 32768 + so) = Agl[goff];
            *(uint4*)(smem + 49152 + so) = Bgl[goff];
        }
        __syncthreads();

        uint32_t sAh = sbase, sBh = sbase + 16384, sAl = sbase + 32768, sBl = sbase + 49152;
#pragma unroll
        for (int ks = 0; ks < 4; ks++) {
            int k0 = ks * 16;
            uint32_t ah[4][4], al[4][4];
#pragma unroll
            for (int mt = 0; mt < 4; mt++) {
                int rowA = m0w + mt * 16 + rowA_off;
                uint32_t off = SWZ(rowA * 128 + (k0 + kA_off) * 2);
                LDSM_X4(ah[mt][0], ah[mt][1], ah[mt][2], ah[mt][3], sAh + off);
                LDSM_X4(al[mt][0], al[mt][1], al[mt][2], al[mt][3], sAl + off);
            }
            uint32_t bh[2][4], bl[2][4];
#pragma unroll
            for (int nt2 = 0; nt2 < 2; nt2++) {
                int rowB = n0w + nt2 * 16 + rowB_off;
                uint32_t off = SWZ(rowB * 128 + (k0 + kB_off) * 2);
                LDSM_X4(bh[nt2][0], bh[nt2][1], bh[nt2][2], bh[nt2][3], sBh + off);
                LDSM_X4(bl[nt2][0], bl[nt2][1], bl[nt2][2], bl[nt2][3], sBl + off);
            }
#pragma unroll
            for (int mt = 0; mt < 4; mt++) {
#pragma unroll
                for (int nt = 0; nt < 4; nt++) {
                    uint32_t bh0 = bh[nt >> 1][(nt & 1) * 2 + 0];
                    uint32_t bh1 = bh[nt >> 1][(nt & 1) * 2 + 1];
                    uint32_t bl0 = bl[nt >> 1][(nt & 1) * 2 + 0];
                    uint32_t bl1 = bl[nt >> 1][(nt & 1) * 2 + 1];
                    float* c = acc[mt][nt];
                    MMA_BF16(c[0], c[1], c[2], c[3],
                             ah[mt][0], ah[mt][1], ah[mt][2], ah[mt][3], bh0, bh1);
                    MMA_BF16(c[0], c[1], c[2], c[3],
                             ah[mt][0], ah[mt][1], ah[mt][2], ah[mt][3], bl0, bl1);
                    MMA_BF16(c[0], c[1], c[2], c[3],
                             al[mt][0], al[mt][1], al[mt][2], al[mt][3], bh0, bh1);
                }
            }
        }
    }
    __syncthreads();

    float* Ep = (float*)smem + wid * (64 * 34);
    int lr = lane >> 2, lc2 = (lane & 3) * 2;
#pragma unroll
    for (int mt = 0; mt < 4; mt++) {
#pragma unroll
        for (int nt = 0; nt < 4; nt++) {
            int r0 = mt * 16 + lr;
            int col = nt * 8 + lc2;
            *(float2*)&Ep[r0 * 34 + col] = make_float2(acc[mt][nt][0], acc[mt][nt][1]);
            *(float2*)&Ep[(r0 + 8) * 34 + col] = make_float2(acc[mt][nt][2], acc[mt][nt][3]);
        }
    }
    __syncwarp();

    int t = blockIdx.y * 2 + warp_m;
    int halfl = lane >> 4, b4 = lane & 15;
#pragma unroll
    for (int c = 0; c < 16; c++) {
        int n_local = c * 2 + halfl;
        int n = bn + n0w + n_local;
        float bias = (n < 1024) ? __ldg(&bf[n]) : __ldg(&br[n - 1024]);
        float4 v;
        v.x = Ep[(b4 * 4 + 0) * 34 + n_local] + bias;
        v.y = Ep[(b4 * 4 + 1) * 34 + n_local] + bias;
        v.z = Ep[(b4 * 4 + 2) * 34 + n_local] + bias;
        v.w = Ep[(b4 * 4 + 3) * 34 + n_local] + bias;
        *(float4*)&g_gx[((size_t)t * N2 + n) * 64 + b4 * 4] = v;
    }
}

// ---------------- per-direction, per-step arrival barrier (round-9 style) ---
__device__ __forceinline__ void grid_barrier(int dir, int step) {
    __syncthreads();
    if (threadIdx.x == 0) {
        __threadfence();
        atomicAdd(&g_cnt[dir][step], 1u);
        volatile unsigned* c = &g_cnt[dir][step];
        while (*c < 64u) {}
    }
    __syncthreads();
}

// ---------------- persistent bidirectional LSTM ----------------
// Counter barrier (round 9) + cp.async two-half h stage overlapping the GEMV.
#define LSTM_SMEM ((16 * 260 + 64 * 260 + 16 * 68) * 4)
__global__ __launch_bounds__(256, 1) void lstm_kernel(const float* __restrict__ whh_f,
                                                      const float* __restrict__ whh_r) {
    extern __shared__ float sm[];
    float* Ws = sm;                          // [16][260]
    float* Hs = sm + 16 * 260;               // [64][260]
    float* Pre = sm + 16 * 260 + 64 * 260;   // [16][68]

    int dir = blockIdx.x >> 6;
    int u0 = (blockIdx.x & 63) * 4;
    const float* whh = dir ? whh_r : whh_f;
    int tid = threadIdx.x;
    uint32_t hs_u32 = smem_u32(Hs);

    int lane = tid & 31, w = tid >> 5;
    int r = lane & 15;
    int bh = lane >> 4;
    int bbase = w * 8 + bh * 4;
    int ab = tid & 63, au = tid >> 6;

    for (int i = tid; i < 16 * 256; i += 256) {
        int rr = i >> 8, k = i & 255;
        int g = rr >> 2, jj = rr & 3;
        Ws[rr * 260 + k] = whh[(size_t)(g * 256 + u0 + jj) * 256 + k];
    }

    float c = 0.0f;
    int p = 0;

    for (int step = 0; step < 128; step++) {
        int t = dir ? (127 - step) : step;

        // prefetch gx for this step (latency hides under barrier wait)
        size_t gxb = ((size_t)t * N2 + dir * 1024 + u0 + au) * 64 + ab;
        float ga0 = g_gx[gxb + 0 * 256 * 64];
        float ga1 = g_gx[gxb + 1 * 256 * 64];
        float ga2 = g_gx[gxb + 2 * 256 * 64];
        float ga3 = g_gx[gxb + 3 * 256 * 64];

        if (step) grid_barrier(dir, step);
        else __syncthreads();  // Ws visible

        // stage prev h in two k-halves via cp.async (L2 path)
        const float* hbase = g_hT + (size_t)(dir * 2 + p) * (BB * HH);
#pragma unroll
        for (int half = 0; half < 2; half++) {
#pragma unroll
            for (int jj = 0; jj < 8; jj++) {
                int c2 = jj * 256 + tid;       // 0..2047
                int b = c2 >> 5, kc = c2 & 31;
                int col = half * 128 + kc * 4;
                CP_ASYNC16(hs_u32 + (b * 260 + col) * 4, hbase + b * 256 + col);
            }
            CP_COMMIT();
        }

        unsigned long long A0 = 0ull, A1 = 0ull, A2 = 0ull, A3 = 0ull;
        const float* wrow = Ws + r * 260;
        const float* h0 = Hs + (bbase + 0) * 260;
        const float* h1 = Hs + (bbase + 1) * 260;
        const float* h2 = Hs + (bbase + 2) * 260;
        const float* h3 = Hs + (bbase + 3) * 260;

        CP_WAIT(1);
        __syncthreads();
        // GEMV k 0..127 (half 1 still in flight)
#pragma unroll 8
        for (int k = 0; k < 128; k += 4) {
            ulonglong2 wv = *(const ulonglong2*)(wrow + k);
            ulonglong2 x0 = *(const ulonglong2*)(h0 + k);
            ulonglong2 x1 = *(const ulonglong2*)(h1 + k);
            ulonglong2 x2 = *(const ulonglong2*)(h2 + k);
            ulonglong2 x3 = *(const ulonglong2*)(h3 + k);
            FMA2(A0, wv.x, x0.x); FMA2(A0, wv.y, x0.y);
            FMA2(A1, wv.x, x1.x); FMA2(A1, wv.y, x1.y);
            FMA2(A2, wv.x, x2.x); FMA2(A2, wv.y, x2.y);
            FMA2(A3, wv.x, x3.x); FMA2(A3, wv.y, x3.y);
        }
        CP_WAIT(0);
        __syncthreads();
        // GEMV k 128..255
#pragma unroll 8
        for (int k = 128; k < 256; k += 4) {
            ulonglong2 wv = *(const ulonglong2*)(wrow + k);
            ulonglong2 x0 = *(const ulonglong2*)(h0 + k);
            ulonglong2 x1 = *(const ulonglong2*)(h1 + k);
            ulonglong2 x2 = *(const ulonglong2*)(h2 + k);
            ulonglong2 x3 = *(const ulonglong2*)(h3 + k);
            FMA2(A0, wv.x, x0.x); FMA2(A0, wv.y, x0.y);
            FMA2(A1, wv.x, x1.x); FMA2(A1, wv.y, x1.y);
            FMA2(A2, wv.x, x2.x); FMA2(A2, wv.y, x2.y);
            FMA2(A3, wv.x, x3.x); FMA2(A3, wv.y, x3.y);
        }
        {
            float2 f0 = unpk(A0), f1 = unpk(A1), f2 = unpk(A2), f3 = unpk(A3);
            Pre[r * 68 + bbase + 0] = f0.x + f0.y;
            Pre[r * 68 + bbase + 1] = f1.x + f1.y;
            Pre[r * 68 + bbase + 2] = f2.x + f2.y;
            Pre[r * 68 + bbase + 3] = f3.x + f3.y;
        }
        __syncthreads();

        float a0 = ga0 + Pre[(0 * 4 + au) * 68 + ab];
        float a1 = ga1 + Pre[(1 * 4 + au) * 68 + ab];
        float a2 = ga2 + Pre[(2 * 4 + au) * 68 + ab];
        float a3 = ga3 + Pre[(3 * 4 + au) * 68 + ab];

        float ig = sigf(a0), fg = sigf(a1), gg = tanhf(a2), og = sigf(a3);
        c = fg * c + ig * gg;
        float h = og * tanhf(c);

        int pn = p ^ 1;
        g_hT[(size_t)(dir * 2 + pn) * (BB * HH) + ab * 256 + (u0 + au)] = h;
        g_hseq[((size_t)t * 512 + dir * 256 + u0 + au) * 64 + ab] = h;
        p = pn;
    }
}

// ---------------- emission: em = h @ lin_w^T + lin_b ----------------
#define EM_SMEM (NCL * 512 * 4)
__global__ __launch_bounds__(256) void emission_kernel(const float* __restrict__ lin_w,
                                                       const float* __restrict__ lin_b) {
    extern __shared__ float EWs[];
    int t = blockIdx.x;
    int tid = threadIdx.x;
    for (int i = tid; i < NCL * 512; i += 256) EWs[i] = lin_w[i];
    __syncthreads();

    int b = tid & 63, cg = tid >> 6;
    float acc[7];
#pragma unroll
    for (int ci = 0; ci < 7; ci++) {
        int c0 = cg * 7 + ci;
        acc[ci] = (c0 < NCL) ? lin_b[c0] : 0.0f;
    }
    const float* hp = g_hseq + (size_t)t * 512 * 64 + b;
#pragma unroll 4
    for (int u = 0; u < 512; u++) {
        float hv = hp[(size_t)u * 64];
#pragma unroll
        for (int ci = 0; ci < 7; ci++) {
            int c0 = cg * 7 + ci;
            if (c0 < NCL) acc[ci] += hv * EWs[c0 * 512 + u];
        }
    }
#pragma unroll
    for (int ci = 0; ci < 7; ci++) {
        int c0 = cg * 7 + ci;
        if (c0 < NCL) g_em[((size_t)t * 64 + b) * NCL + c0] = acc[ci];
    }
}

// ---------------- CRF NLL (one block per batch, 1 warp) ----------------
__global__ __launch_bounds__(32) void crf_kernel(const int* __restrict__ tag,
                                                 const float* __restrict__ start_t,
                                                 const float* __restrict__ end_t,
                                                 const float* __restrict__ trans) {
    int b = blockIdx.x;
    int lane = threadIdx.x;

    __shared__ float tr[NCL * NCL];
    __shared__ float alphas[32];

    for (int i = lane; i < NCL * NCL; i += 32) tr[i] = trans[i];
    __syncwarp();

    float myscore = 0.0f;
    int mylen = 0;
    for (int t = lane; t < SS; t += 32) {
        int mk = g_mask[b * SS + t];
        mylen += mk;
        int tgt = tag[b * SS + t];
        if (t == 0) {
            myscore += start_t[tgt] + g_em[(size_t)b * NCL + tgt];
        } else if (mk) {
            int tgp = tag[b * SS + t - 1];
            myscore += tr[tgp * NCL + tgt] + g_em[((size_t)t * 64 + b) * NCL + tgt];
        }
    }
#pragma unroll
    for (int off = 16; off > 0; off >>= 1) {
        myscore += __shfl_xor_sync(0xFFFFFFFFu, myscore, off);
        mylen += __shfl_xor_sync(0xFFFFFFFFu, mylen, off);
    }
    float score = 0.0f;
    if (lane == 0) {
        int last = mylen - 1;
        score = myscore + end_t[tag[b * SS + last]];
    }

    if (lane < NCL) alphas[lane] = start_t[lane] + g_em[(size_t)b * NCL + lane];
    __syncwarp();

    for (int t = 1; t < SS; t++) {
        int mk = g_mask[b * SS + t];
        float nxt = 0.0f;
        if (lane < NCL) {
            float emv = g_em[((size_t)t * 64 + b) * NCL + lane];
            float m = -1e30f;
#pragma unroll
            for (int i = 0; i < NCL; i++) m = fmaxf(m, alphas[i] + tr[i * NCL + lane]);
            float s = 0.0f;
#pragma unroll
            for (int i = 0; i < NCL; i++) s += __expf(alphas[i] + tr[i * NCL + lane] - m);
            nxt = m + __logf(s) + emv;
        }
        __syncwarp();
        if (lane < NCL && mk) alphas[lane] = nxt;
        __syncwarp();
    }

    float v = (lane < NCL) ? alphas[lane] + end_t[lane] : -1e30f;
    float m = v;
#pragma unroll
    for (int off = 16; off > 0; off >>= 1) m = fmaxf(m, __shfl_xor_sync(0xFFFFFFFFu, m, off));
    float s = __expf(v - m);
#pragma unroll
    for (int off = 16; off > 0; off >>= 1) s += __shfl_xor_sync(0xFFFFFFFFu, s, off);
    if (lane == 0) {
        float logZ = m + __logf(s);
        g_nll[b] = -(score - logZ);
    }
}

// ---------------- deterministic final sum ----------------
__global__ void sum_kernel(float* out) {
    int lane = threadIdx.x;
    float s = g_nll[lane] + g_nll[lane + 32];
#pragma unroll
    for (int off = 16; off > 0; off >>= 1) s += __shfl_xor_sync(0xFFFFFFFFu, s, off);
    if (lane == 0) out[0] = s;
}

// ---------------- launch ----------------
extern "C" void kernel_launch(void* const* d_in, const int* in_sizes, int n_in,
                              void* d_out, int out_size) {
    const float* word_table = (const float*)d_in[0];
    const float* char_table = (const float*)d_in[1];
    const float* conv_w     = (const float*)d_in[2];
    const float* conv_b     = (const float*)d_in[3];
    const float* w_ih_f     = (const float*)d_in[4];
    const float* w_hh_f     = (const float*)d_in[5];
    const float* b_f        = (const float*)d_in[6];
    const float* w_ih_r     = (const float*)d_in[7];
    const float* w_hh_r     = (const float*)d_in[8];
    const float* b_r        = (const float*)d_in[9];
    const float* lin_w      = (const float*)d_in[10];
    const float* lin_b      = (const float*)d_in[11];
    const float* start_t    = (const float*)d_in[12];
    const float* end_t      = (const float*)d_in[13];
    const float* trans      = (const float*)d_in[14];
    const int*   sent       = (const int*)d_in[15];
    const int*   word       = (const int*)d_in[16];
    const int*   tag        = (const int*)d_in[17];
    const unsigned* mask    = (const unsigned*)d_in[18];
    float* out = (float*)d_out;

    static int smem_set = 0;
    if (!smem_set) {
        cudaFuncSetAttribute(lstm_kernel, cudaFuncAttributeMaxDynamicSharedMemorySize, LSTM_SMEM);
        cudaFuncSetAttribute(emission_kernel, cudaFuncAttributeMaxDynamicSharedMemorySize, EM_SMEM);
        cudaFuncSetAttribute(gemm_gx_mma_kernel, cudaFuncAttributeMaxDynamicSharedMemorySize, GX_SMEM);
        smem_set = 1;
    }

    init_kernel<<<8, 256>>>();
    mask_convert_kernel<<<32, 256>>>(mask);
    pad_w_kernel<<<(N2 * KPAD + 255) / 256, 256>>>(w_ih_f, w_ih_r);
    embed_conv_kernel<<<2048, 128>>>(word_table, char_table, conv_w, conv_b, sent, word);
    gemm_gx_mma_kernel<<<dim3(16, 64), 256, GX_SMEM>>>(b_f, b_r);
    lstm_kernel<<<128, 256, LSTM_SMEM>>>(w_hh_f, w_hh_r);
    emission_kernel<<<128, 256, EM_SMEM>>>(lin_w, lin_b);
    crf_kernel<<<64, 32>>>(tag, start_t, end_t, trans);
    sum_kernel<<<1, 32>>>(out);
}

// round 13
// speedup vs baseline: 1.2317x; 1.0012x over previous
#include <cuda_runtime.h>
#include <cuda_bf16.h>
#include <math.h>
#include <stdint.h>

// ---------------- problem constants ----------------
#define BB 64      // batch
#define SS 128     // seq len
#define LW 20      // chars per word
#define CE 30      // char emb
#define CC 30      // char conv channels
#define WE 300     // word emb
#define HH 256     // hidden
#define NCL 25     // num classes
#define FF 330     // feature = WE + CC
#define KPAD 384   // padded K for bf16 MMA (6 chunks of 64)
#define NROW 8192  // S*B token rows
#define N2 2048    // 2 dirs * 4H

// ---------------- packed f32x2 helpers ----------------
#define FMA2(d, a, b) asm("fma.rn.f32x2 %0, %1, %2, %0;" : "+l"(d) : "l"(a), "l"(b))

__device__ __forceinline__ float2 unpk(unsigned long long v) {
    float2 f;
    asm("mov.b64 {%0, %1}, %2;" : "=f"(f.x), "=f"(f.y) : "l"(v));
    return f;
}

// ---------------- mma.sync / async helpers (baseline PTX, sm_103-safe) ------
__device__ __forceinline__ uint32_t smem_u32(const void* p) {
    uint32_t a;
    asm("{ .reg .u64 t; cvta.to.shared.u64 t, %1; cvt.u32.u64 %0, t; }" : "=r"(a) : "l"(p));
    return a;
}
#define SWZ(o) ((o) ^ (((o) >> 3) & 0x70))

#define LDSM_X4(r0, r1, r2, r3, a) \
    asm volatile("ldmatrix.sync.aligned.m8n8.x4.shared.b16 {%0,%1,%2,%3}, [%4];" \
                 : "=r"(r0), "=r"(r1), "=r"(r2), "=r"(r3) : "r"(a))

#define MMA_BF16(c0, c1, c2, c3, a0, a1, a2, a3, b0, b1) \
    asm volatile("mma.sync.aligned.m16n8k16.row.col.f32.bf16.bf16.f32 " \
                 "{%0,%1,%2,%3}, {%4,%5,%6,%7}, {%8,%9}, {%0,%1,%2,%3};" \
                 : "+f"(c0), "+f"(c1), "+f"(c2), "+f"(c3) \
                 : "r"(a0), "r"(a1), "r"(a2), "r"(a3), "r"(b0), "r"(b1))

#define CP_ASYNC16(dst, src) \
    asm volatile("cp.async.cg.shared.global [%0], [%1], 16;" :: "r"(dst), "l"(src))
#define CP_COMMIT() asm volatile("cp.async.commit_group;")
#define CP_WAIT(n)  asm volatile("cp.async.wait_group %0;" :: "n"(n))

// ---------------- static device scratch ----------------
__device__ __align__(16) __nv_bfloat16 g_featH[(size_t)NROW * KPAD];  // hi
__device__ __align__(16) __nv_bfloat16 g_featL[(size_t)NROW * KPAD];  // lo residual
__device__ __align__(16) __nv_bfloat16 g_wH[(size_t)N2 * KPAD];       // hi
__device__ __align__(16) __nv_bfloat16 g_wL[(size_t)N2 * KPAD];       // lo residual
__device__ float g_gx[(size_t)NROW * N2];     // [(t*2048+col)*64 + b]
__device__ float g_hT[2 * 2 * BB * HH];       // [dir][parity][b][u]
__device__ float g_hseq[(size_t)NROW * 512];  // [(t*512+ug)*64 + b]
__device__ float g_em[(size_t)NROW * NCL];    // [(t*64+b)*25 + c]
__device__ int   g_mask[BB * SS];             // [b][t]
__device__ float g_nll[BB];
__device__ unsigned g_cnt8[2][SS][8][32];     // 8 sub-counters/step, 128B apart

__device__ __forceinline__ float sigf(float x) { return 1.0f / (1.0f + __expf(-x)); }

__device__ __forceinline__ void split_bf16(float v, __nv_bfloat16& hi, __nv_bfloat16& lo) {
    hi = __float2bfloat16_rn(v);
    lo = __float2bfloat16_rn(v - __bfloat162float(hi));
}

// ---------------- init ----------------
__global__ void init_kernel() {
    int tid = blockIdx.x * blockDim.x + threadIdx.x;
    int nt = blockDim.x * gridDim.x;
    for (int i = tid; i < 2 * SS * 8 * 32; i += nt) ((unsigned*)g_cnt8)[i] = 0u;
    for (int i = tid; i < 2 * 2 * BB * HH; i += nt) g_hT[i] = 0.0f;
    if (tid < BB) g_nll[tid] = 0.0f;
}

// ---------------- mask dtype detect + convert ----------------
__global__ void mask_convert_kernel(const unsigned* __restrict__ m) {
    unsigned v0 = m[0];
    int mode;  // 0 = int32, 1 = bytes, 2 = float32
    if (v0 == 0x01010101u) mode = 1;
    else if (v0 == 0x3F800000u) mode = 2;
    else mode = 0;
    int tid = blockIdx.x * blockDim.x + threadIdx.x;
    if (tid >= BB * SS) return;
    int v;
    if (mode == 1) {
        const unsigned char* mb = (const unsigned char*)m;
        v = (mb[tid] != 0) ? 1 : 0;
    } else if (mode == 2) {
        const float* mf = (const float*)m;
        v = (mf[tid] != 0.0f) ? 1 : 0;
    } else {
        v = (m[tid] != 0u) ? 1 : 0;
    }
    g_mask[tid] = v;
}

// ---------------- pad w_ih into bf16 hi/lo [2048][384] ----------------
__global__ void pad_w_kernel(const float* __restrict__ w_ih_f,
                             const float* __restrict__ w_ih_r) {
    int idx = blockIdx.x * blockDim.x + threadIdx.x;
    if (idx >= N2 * KPAD) return;
    int r = idx / KPAD, k = idx - r * KPAD;
    float v = 0.0f;
    if (k < FF) v = (r < 1024) ? w_ih_f[r * FF + k] : w_ih_r[(r - 1024) * FF + k];
    __nv_bfloat16 hi, lo;
    split_bf16(v, hi, lo);
    g_wH[idx] = hi;
    g_wL[idx] = lo;
}

// ---------------- char CNN + embedding concat -> featH/L (bf16) -------------
__global__ __launch_bounds__(128) void embed_conv_kernel(
    const float* __restrict__ word_table, const float* __restrict__ char_table,
    const float* __restrict__ conv_w, const float* __restrict__ conv_b,
    const int* __restrict__ sent, const int* __restrict__ word) {
    __shared__ float wsm[CC * CE * 3];   // 2700
    __shared__ float psm[4][22 * 32];    // per-warp padded char emb [pos][ic(32)]
    __shared__ int   cids[4][LW];

    int tid = threadIdx.x, w = tid >> 5, lane = tid & 31;
    int tok = blockIdx.x * 4 + w;        // tok = b*128 + s
    int b = tok >> 7, s = tok & 127;
    int row = s * BB + b;

    for (int i = tid; i < CC * CE * 3; i += 128) wsm[i] = conv_w[i];
    float* pw = psm[w];
    for (int i = lane; i < 22 * 32; i += 32) pw[i] = 0.0f;
    if (lane < LW) cids[w][lane] = word[tok * LW + lane];
    __syncthreads();

    for (int pos = 0; pos < LW; pos++) {
        if (lane < CE) {
            int c = cids[w][pos];
            pw[(pos + 1) * 32 + lane] = (c == 0) ? 0.0f : char_table[c * CE + lane];
        }
    }

    // word embedding copy (fp32 -> bf16 hi/lo)
    int widx = sent[tok];
    __nv_bfloat16* frowH = g_featH + (size_t)row * KPAD;
    __nv_bfloat16* frowL = g_featL + (size_t)row * KPAD;
    {
        const float4* wt = (const float4*)(word_table + (size_t)widx * WE);
        for (int j = lane; j < 75; j += 32) {
            float4 v = wt[j];
            __nv_bfloat16 h0, l0, h1, l1, h2, l2, h3, l3;
            split_bf16(v.x, h0, l0); split_bf16(v.y, h1, l1);
            split_bf16(v.z, h2, l2); split_bf16(v.w, h3, l3);
            __nv_bfloat162 ph0; ph0.x = h0; ph0.y = h1;
            __nv_bfloat162 ph1; ph1.x = h2; ph1.y = h3;
            __nv_bfloat162 pl0; pl0.x = l0; pl0.y = l1;
            __nv_bfloat162 pl1; pl1.x = l2; pl1.y = l3;
            *(__nv_bfloat162*)(frowH + j * 4) = ph0;
            *(__nv_bfloat162*)(frowH + j * 4 + 2) = ph1;
            *(__nv_bfloat162*)(frowL + j * 4) = pl0;
            *(__nv_bfloat162*)(frowL + j * 4 + 2) = pl1;
        }
    }
    __syncwarp();

    // conv: lane oc, weights in regs, x broadcast
    int oc = (lane < CC) ? lane : 0;
    float wreg[3][32];
#pragma unroll
    for (int k = 0; k < 3; k++)
#pragma unroll
        for (int ic = 0; ic < 32; ic++)
            wreg[k][ic] = (ic < CC) ? wsm[oc * 90 + ic * 3 + k] : 0.0f;

    float m = -1e30f;
    for (int t = 0; t < LW; t++) {
        float asum = 0.0f;
#pragma unroll
        for (int k = 0; k < 3; k++) {
            const float4* xr = (const float4*)(pw + (t + k) * 32);
            float acc = 0.0f;
#pragma unroll
            for (int j = 0; j < 8; j++) {
                float4 x = xr[j];
                acc += x.x * wreg[k][j * 4 + 0] + x.y * wreg[k][j * 4 + 1]
                     + x.z * wreg[k][j * 4 + 2] + x.w * wreg[k][j * 4 + 3];
            }
            asum += acc;
        }
        m = fmaxf(m, asum);
    }
    if (lane < CC) {
        __nv_bfloat16 hi, lo;
        split_bf16(m + conv_b[lane], hi, lo);
        frowH[WE + lane] = hi;
        frowL[WE + lane] = lo;
    }
    if (lane < 27) {
        __nv_bfloat162 z; z.x = __float2bfloat16_rn(0.0f); z.y = z.x;
        *(__nv_bfloat162*)(frowH + FF + 2 * lane) = z;
        *(__nv_bfloat162*)(frowL + FF + 2 * lane) = z;
    }
}

// ---------------- gx GEMM via mma.sync bf16, split hi/lo 3-pass -------------
#define GX_SMEM 69632
__global__ __launch_bounds__(256) void gemm_gx_mma_kernel(const float* __restrict__ bf,
                                                          const float* __restrict__ br) {
    extern __shared__ char smem[];
    uint32_t sbase = smem_u32(smem);
    int tid = threadIdx.x;
    int wid = tid >> 5, lane = tid & 31;
    int bn = blockIdx.x * 128;
    int bm = blockIdx.y * 128;

    int warp_m = wid & 1, warp_n = wid >> 1;
    int m0w = warp_m * 64, n0w = warp_n * 32;
    int g = lane >> 3;
    int rowA_off = (lane & 7) + (g & 1) * 8;
    int kA_off = (g >> 1) * 8;
    int rowB_off = (lane & 7) + (g >> 1) * 8;
    int kB_off = (g & 1) * 8;

    float acc[4][4][4];
#pragma unroll
    for (int i = 0; i < 4; i++)
#pragma unroll
        for (int j = 0; j < 4; j++)
#pragma unroll
            for (int q = 0; q < 4; q++) acc[i][j][q] = 0.0f;

    int srow = tid >> 3, su = tid & 7;
    const uint4* Agh = (const uint4*)(g_featH + (size_t)(bm + srow) * KPAD) + su;
    const uint4* Agl = (const uint4*)(g_featL + (size_t)(bm + srow) * KPAD) + su;
    const uint4* Bgh = (const uint4*)(g_wH + (size_t)(bn + srow) * KPAD) + su;
    const uint4* Bgl = (const uint4*)(g_wL + (size_t)(bn + srow) * KPAD) + su;

#pragma unroll 1
    for (int kc = 0; kc < 6; kc++) {
        if (kc > 0) __syncthreads();
#pragma unroll
        for (int j = 0; j < 4; j++) {
            size_t goff = (size_t)kc * 8 + (size_t)j * 32 * 48;
            uint32_t so = SWZ((srow + j * 32) * 128 + su * 16);
            *(uint4*)(smem + 0 + so)     = Agh[goff];
            *(uint4*)(smem + 16384 + so) = Bgh[goff];
            *(uint4*)(smem + 32768 + so) = Agl[goff];
            *(uint4*)(smem + 49152 + so) = Bgl[goff];
        }
        __syncthreads();

        uint32_t sAh = sbase, sBh = sbase + 16384, sAl = sbase + 32768, sBl = sbase + 49152;
#pragma unroll
        for (int ks = 0; ks < 4; ks++) {
            int k0 = ks * 16;
            uint32_t ah[4][4], al[4][4];
#pragma unroll
            for (int mt = 0; mt < 4; mt++) {
                int rowA = m0w + mt * 16 + rowA_off;
                uint32_t off = SWZ(rowA * 128 + (k0 + kA_off) * 2);
                LDSM_X4(ah[mt][0], ah[mt][1], ah[mt][2], ah[mt][3], sAh + off);
                LDSM_X4(al[mt][0], al[mt][1], al[mt][2], al[mt][3], sAl + off);
            }
            uint32_t bh[2][4], bl[2][4];
#pragma unroll
            for (int nt2 = 0; nt2 < 2; nt2++) {
                int rowB = n0w + nt2 * 16 + rowB_off;
                uint32_t off = SWZ(rowB * 128 + (k0 + kB_off) * 2);
                LDSM_X4(bh[nt2][0], bh[nt2][1], bh[nt2][2], bh[nt2][3], sBh + off);
                LDSM_X4(bl[nt2][0], bl[nt2][1], bl[nt2][2], bl[nt2][3], sBl + off);
            }
#pragma unroll
            for (int mt = 0; mt < 4; mt++) {
#pragma unroll
                for (int nt = 0; nt < 4; nt++) {
                    uint32_t bh0 = bh[nt >> 1][(nt & 1) * 2 + 0];
                    uint32_t bh1 = bh[nt >> 1][(nt & 1) * 2 + 1];
                    uint32_t bl0 = bl[nt >> 1][(nt & 1) * 2 + 0];
                    uint32_t bl1 = bl[nt >> 1][(nt & 1) * 2 + 1];
                    float* c = acc[mt][nt];
                    MMA_BF16(c[0], c[1], c[2], c[3],
                             ah[mt][0], ah[mt][1], ah[mt][2], ah[mt][3], bh0, bh1);
                    MMA_BF16(c[0], c[1], c[2], c[3],
                             ah[mt][0], ah[mt][1], ah[mt][2], ah[mt][3], bl0, bl1);
                    MMA_BF16(c[0], c[1], c[2], c[3],
                             al[mt][0], al[mt][1], al[mt][2], al[mt][3], bh0, bh1);
                }
            }
        }
    }
    __syncthreads();

    float* Ep = (float*)smem + wid * (64 * 34);
    int lr = lane >> 2, lc2 = (lane & 3) * 2;
#pragma unroll
    for (int mt = 0; mt < 4; mt++) {
#pragma unroll
        for (int nt = 0; nt < 4; nt++) {
            int r0 = mt * 16 + lr;
            int col = nt * 8 + lc2;
            *(float2*)&Ep[r0 * 34 + col] = make_float2(acc[mt][nt][0], acc[mt][nt][1]);
            *(float2*)&Ep[(r0 + 8) * 34 + col] = make_float2(acc[mt][nt][2], acc[mt][nt][3]);
        }
    }
    __syncwarp();

    int t = blockIdx.y * 2 + warp_m;
    int halfl = lane >> 4, b4 = lane & 15;
#pragma unroll
    for (int c = 0; c < 16; c++) {
        int n_local = c * 2 + halfl;
        int n = bn + n0w + n_local;
        float bias = (n < 1024) ? __ldg(&bf[n]) : __ldg(&br[n - 1024]);
        float4 v;
        v.x = Ep[(b4 * 4 + 0) * 34 + n_local] + bias;
        v.y = Ep[(b4 * 4 + 1) * 34 + n_local] + bias;
        v.z = Ep[(b4 * 4 + 2) * 34 + n_local] + bias;
        v.w = Ep[(b4 * 4 + 3) * 34 + n_local] + bias;
        *(float4*)&g_gx[((size_t)t * N2 + n) * 64 + b4 * 4] = v;
    }
}

// ---------------- split-counter grid barrier (8 lines, 8 arrivals each) -----
__device__ __forceinline__ void grid_barrier(int dir, int step, int bslot) {
    __syncthreads();
    if (threadIdx.x == 0) {
        __threadfence();
        atomicAdd(&g_cnt8[dir][step][bslot & 7][0], 1u);
    }
    if (threadIdx.x < 8) {
        volatile unsigned* c = &g_cnt8[dir][step][threadIdx.x][0];
        while (*c < 8u) {}
    }
    __syncthreads();
}

// ---------------- persistent bidirectional LSTM ----------------
// Counter barrier (8-way split) + cp.async two-half stage + shuffle activation.
#define LSTM_SMEM ((16 * 260 + 64 * 260) * 4)
__global__ __launch_bounds__(256, 1) void lstm_kernel(const float* __restrict__ whh_f,
                                                      const float* __restrict__ whh_r) {
    extern __shared__ float sm[];
    float* Ws = sm;              // [16][260]
    float* Hs = sm + 16 * 260;   // [64][260]

    int dir = blockIdx.x >> 6;
    int bslot = blockIdx.x & 63;
    int u0 = bslot * 4;
    const float* whh = dir ? whh_r : whh_f;
    int tid = threadIdx.x;
    uint32_t hs_u32 = smem_u32(Hs);

    int lane = tid & 31, w = tid >> 5;
    // GEMV roles
    int r = lane & 15;
    int bh = lane >> 4;
    int bbase = w * 8 + bh * 4;
    // activation roles (same warp): lane owns (u_act, b_act)
    int u_act = lane >> 3;              // 0..3
    int b_act = w * 8 + (lane & 7);     // batch
    int vi = lane & 3;                  // value index within source lane
    int src_hi = ((lane >> 2) & 1) << 4;

    for (int i = tid; i < 16 * 256; i += 256) {
        int rr = i >> 8, k = i & 255;
        int g = rr >> 2, jj = rr & 3;
        Ws[rr * 260 + k] = whh[(size_t)(g * 256 + u0 + jj) * 256 + k];
    }

    float c = 0.0f;
    int p = 0;

    for (int step = 0; step < 128; step++) {
        int t = dir ? (127 - step) : step;

        // prefetch gx for this step's (u_act, b_act)
        size_t gxb = ((size_t)t * N2 + dir * 1024 + u0 + u_act) * 64 + b_act;
        float ga0 = g_gx[gxb + 0 * 256 * 64];
        float ga1 = g_gx[gxb + 1 * 256 * 64];
        float ga2 = g_gx[gxb + 2 * 256 * 64];
        float ga3 = g_gx[gxb + 3 * 256 * 64];

        if (step) grid_barrier(dir, step, bslot);
        else __syncthreads();  // Ws visible

        // stage prev h in two k-halves via cp.async (L2 path)
        const float* hbase = g_hT + (size_t)(dir * 2 + p) * (BB * HH);
#pragma unroll
        for (int half = 0; half < 2; half++) {
#pragma unroll
            for (int jj = 0; jj < 8; jj++) {
                int c2 = jj * 256 + tid;       // 0..2047
                int b = c2 >> 5, kc = c2 & 31;
                int col = half * 128 + kc * 4;
                CP_ASYNC16(hs_u32 + (b * 260 + col) * 4, hbase + b * 256 + col);
            }
            CP_COMMIT();
        }

        unsigned long long A0 = 0ull, A1 = 0ull, A2 = 0ull, A3 = 0ull;
        const float* wrow = Ws + r * 260;
        const float* h0 = Hs + (bbase + 0) * 260;
        const float* h1 = Hs + (bbase + 1) * 260;
        const float* h2 = Hs + (bbase + 2) * 260;
        const float* h3 = Hs + (bbase + 3) * 260;

        CP_WAIT(1);
        __syncthreads();
#pragma unroll 8
        for (int k = 0; k < 128; k += 4) {
            ulonglong2 wv = *(const ulonglong2*)(wrow + k);
            ulonglong2 x0 = *(const ulonglong2*)(h0 + k);
            ulonglong2 x1 = *(const ulonglong2*)(h1 + k);
            ulonglong2 x2 = *(const ulonglong2*)(h2 + k);
            ulonglong2 x3 = *(const ulonglong2*)(h3 + k);
            FMA2(A0, wv.x, x0.x); FMA2(A0, wv.y, x0.y);
            FMA2(A1, wv.x, x1.x); FMA2(A1, wv.y, x1.y);
            FMA2(A2, wv.x, x2.x); FMA2(A2, wv.y, x2.y);
            FMA2(A3, wv.x, x3.x); FMA2(A3, wv.y, x3.y);
        }
        CP_WAIT(0);
        __syncthreads();
#pragma unroll 8
        for (int k = 128; k < 256; k += 4) {
            ulonglong2 wv = *(const ulonglong2*)(wrow + k);
            ulonglong2 x0 = *(const ulonglong2*)(h0 + k);
            ulonglong2 x1 = *(const ulonglong2*)(h1 + k);
            ulonglong2 x2 = *(const ulonglong2*)(h2 + k);
            ulonglong2 x3 = *(const ulonglong2*)(h3 + k);
            FMA2(A0, wv.x, x0.x); FMA2(A0, wv.y, x0.y);
            FMA2(A1, wv.x, x1.x); FMA2(A1, wv.y, x1.y);
            FMA2(A2, wv.x, x2.x); FMA2(A2, wv.y, x2.y);
            FMA2(A3, wv.x, x3.x); FMA2(A3, wv.y, x3.y);
        }

        // horizontal sums (identical math/order to Pre version)
        float2 f0 = unpk(A0), f1 = unpk(A1), f2 = unpk(A2), f3 = unpk(A3);
        float s0 = f0.x + f0.y;
        float s1 = f1.x + f1.y;
        float s2 = f2.x + f2.y;
        float s3 = f3.x + f3.y;

        // in-warp exchange: activation lane (u_act, b_act) pulls 4 gate sums
        float gate[4];
#pragma unroll
        for (int g = 0; g < 4; g++) {
            int src = (g * 4 + u_act) | src_hi;
            float t0 = __shfl_sync(0xFFFFFFFFu, s0, src);
            float t1 = __shfl_sync(0xFFFFFFFFu, s1, src);
            float t2 = __shfl_sync(0xFFFFFFFFu, s2, src);
            float t3 = __shfl_sync(0xFFFFFFFFu, s3, src);
            gate[g] = (vi == 0) ? t0 : (vi == 1) ? t1 : (vi == 2) ? t2 : t3;
        }

        float a0 = ga0 + gate[0];
        float a1 = ga1 + gate[1];
        float a2 = ga2 + gate[2];
        float a3 = ga3 + gate[3];

        float ig = sigf(a0), fg = sigf(a1), gg = tanhf(a2), og = sigf(a3);
        c = fg * c + ig * gg;
        float h = og * tanhf(c);

        int pn = p ^ 1;
        g_hT[(size_t)(dir * 2 + pn) * (BB * HH) + b_act * 256 + (u0 + u_act)] = h;
        g_hseq[((size_t)t * 512 + dir * 256 + u0 + u_act) * 64 + b_act] = h;
        p = pn;
    }
}

// ---------------- emission: em = h @ lin_w^T + lin_b ----------------
#define EM_SMEM (NCL * 512 * 4)
__global__ __launch_bounds__(256) void emission_kernel(const float* __restrict__ lin_w,
                                                       const float* __restrict__ lin_b) {
    extern __shared__ float EWs[];
    int t = blockIdx.x;
    int tid = threadIdx.x;
    for (int i = tid; i < NCL * 512; i += 256) EWs[i] = lin_w[i];
    __syncthreads();

    int b = tid & 63, cg = tid >> 6;
    float acc[7];
#pragma unroll
    for (int ci = 0; ci < 7; ci++) {
        int c0 = cg * 7 + ci;
        acc[ci] = (c0 < NCL) ? lin_b[c0] : 0.0f;
    }
    const float* hp = g_hseq + (size_t)t * 512 * 64 + b;
#pragma unroll 4
    for (int u = 0; u < 512; u++) {
        float hv = hp[(size_t)u * 64];
#pragma unroll
        for (int ci = 0; ci < 7; ci++) {
            int c0 = cg * 7 + ci;
            if (c0 < NCL) acc[ci] += hv * EWs[c0 * 512 + u];
        }
    }
#pragma unroll
    for (int ci = 0; ci < 7; ci++) {
        int c0 = cg * 7 + ci;
        if (c0 < NCL) g_em[((size_t)t * 64 + b) * NCL + c0] = acc[ci];
    }
}

// ---------------- CRF NLL (one block per batch, 1 warp) ----------------
__global__ __launch_bounds__(32) void crf_kernel(const int* __restrict__ tag,
                                                 const float* __restrict__ start_t,
                                                 const float* __restrict__ end_t,
                                                 const float* __restrict__ trans) {
    int b = blockIdx.x;
    int lane = threadIdx.x;

    __shared__ float tr[NCL * NCL];
    __shared__ float alphas[32];

    for (int i = lane; i < NCL * NCL; i += 32) tr[i] = trans[i];
    __syncwarp();

    float myscore = 0.0f;
    int mylen = 0;
    for (int t = lane; t < SS; t += 32) {
        int mk = g_mask[b * SS + t];
        mylen += mk;
        int tgt = tag[b * SS + t];
        if (t == 0) {
            myscore += start_t[tgt] + g_em[(size_t)b * NCL + tgt];
        } else if (mk) {
            int tgp = tag[b * SS + t - 1];
            myscore += tr[tgp * NCL + tgt] + g_em[((size_t)t * 64 + b) * NCL + tgt];
        }
    }
#pragma unroll
    for (int off = 16; off > 0; off >>= 1) {
        myscore += __shfl_xor_sync(0xFFFFFFFFu, myscore, off);
        mylen += __shfl_xor_sync(0xFFFFFFFFu, mylen, off);
    }
    float score = 0.0f;
    if (lane == 0) {
        int last = mylen - 1;
        score = myscore + end_t[tag[b * SS + last]];
    }

    if (lane < NCL) alphas[lane] = start_t[lane] + g_em[(size_t)b * NCL + lane];
    __syncwarp();

    for (int t = 1; t < SS; t++) {
        int mk = g_mask[b * SS + t];
        float nxt = 0.0f;
        if (lane < NCL) {
            float emv = g_em[((size_t)t * 64 + b) * NCL + lane];
            float m = -1e30f;
#pragma unroll
            for (int i = 0; i < NCL; i++) m = fmaxf(m, alphas[i] + tr[i * NCL + lane]);
            float s = 0.0f;
#pragma unroll
            for (int i = 0; i < NCL; i++) s += __expf(alphas[i] + tr[i * NCL + lane] - m);
            nxt = m + __logf(s) + emv;
        }
        __syncwarp();
        if (lane < NCL && mk) alphas[lane] = nxt;
        __syncwarp();
    }

    float v = (lane < NCL) ? alphas[lane] + end_t[lane] : -1e30f;
    float m = v;
#pragma unroll
    for (int off = 16; off > 0; off >>= 1) m = fmaxf(m, __shfl_xor_sync(0xFFFFFFFFu, m, off));
    float s = __expf(v - m);
#pragma unroll
    for (int off = 16; off > 0; off >>= 1) s += __shfl_xor_sync(0xFFFFFFFFu, s, off);
    if (lane == 0) {
        float logZ = m + __logf(s);
        g_nll[b] = -(score - logZ);
    }
}

// ---------------- deterministic final sum ----------------
__global__ void sum_kernel(float* out) {
    int lane = threadIdx.x;
    float s = g_nll[lane] + g_nll[lane + 32];
#pragma unroll
    for (int off = 16; off > 0; off >>= 1) s += __shfl_xor_sync(0xFFFFFFFFu, s, off);
    if (lane == 0) out[0] = s;
}

// ---------------- launch ----------------
extern "C" void kernel_launch(void* const* d_in, const int* in_sizes, int n_in,
                              void* d_out, int out_size) {
    const float* word_table = (const float*)d_in[0];
    const float* char_table = (const float*)d_in[1];
    const float* conv_w     = (const float*)d_in[2];
    const float* conv_b     = (const float*)d_in[3];
    const float* w_ih_f     = (const float*)d_in[4];
    const float* w_hh_f     = (const float*)d_in[5];
    const float* b_f        = (const float*)d_in[6];
    const float* w_ih_r     = (const float*)d_in[7];
    const float* w_hh_r     = (const float*)d_in[8];
    const float* b_r        = (const float*)d_in[9];
    const float* lin_w      = (const float*)d_in[10];
    const float* lin_b      = (const float*)d_in[11];
    const float* start_t    = (const float*)d_in[12];
    const float* end_t      = (const float*)d_in[13];
    const float* trans      = (const float*)d_in[14];
    const int*   sent       = (const int*)d_in[15];
    const int*   word       = (const int*)d_in[16];
    const int*   tag        = (const int*)d_in[17];
    const unsigned* mask    = (const unsigned*)d_in[18];
    float* out = (float*)d_out;

    static int smem_set = 0;
    if (!smem_set) {
        cudaFuncSetAttribute(lstm_kernel, cudaFuncAttributeMaxDynamicSharedMemorySize, LSTM_SMEM);
        cudaFuncSetAttribute(emission_kernel, cudaFuncAttributeMaxDynamicSharedMemorySize, EM_SMEM);
        cudaFuncSetAttribute(gemm_gx_mma_kernel, cudaFuncAttributeMaxDynamicSharedMemorySize, GX_SMEM);
        smem_set = 1;
    }

    init_kernel<<<32, 256>>>();
    mask_convert_kernel<<<32, 256>>>(mask);
    pad_w_kernel<<<(N2 * KPAD + 255) / 256, 256>>>(w_ih_f, w_ih_r);
    embed_conv_kernel<<<2048, 128>>>(word_table, char_table, conv_w, conv_b, sent, word);
    gemm_gx_mma_kernel<<<dim3(16, 64), 256, GX_SMEM>>>(b_f, b_r);
    lstm_kernel<<<128, 256, LSTM_SMEM>>>(w_hh_f, w_hh_r);
    emission_kernel<<<128, 256, EM_SMEM>>>(lin_w, lin_b);
    crf_kernel<<<64, 32>>>(tag, start_t, end_t, trans);
    sum_kernel<<<1, 32>>>(out);
}